// round 6
// baseline (speedup 1.0000x reference)
#include <cuda_runtime.h>
#include <cuda_fp16.h>
#include <cstdint>

#define N_NODES 100000
#define NBLOCKS_E 6250
#define NBLOCKS_G 782                 // ceil(100000/128)
#define SROW 72
#define ABUF (128 * SROW)
#define SMEM_FLOATS (2 * ABUF + 256)
#define SMEM_BYTES (SMEM_FLOATS * 4)

// G = H @ Wh^T  (100096 x 128, fp32) - L2-resident scratch
__device__ float g_G[100096 * 128];

// fp16 B fragments for mma.m16n8k16:
// index = (((half*2 + wn)*8 + ks)*32 + lane)*16 + nt*2 + j
//   -> half2( W[wn*64+nt*8+g][half*128 + ks*16 + 2t + 8j], W[..][..+1] )
__device__ uint32_t g_Bf16[16384];    // 64 KB (Wh half + We half)

__global__ void prep_b16(const float* __restrict__ W) {
    int i = blockIdx.x * 256 + threadIdx.x;   // 0..16383
    int region = i >> 12;                     // half*2 + wn
    int half = region >> 1, wn = region & 1;
    int ks   = (i >> 9) & 7;
    int lane = (i >> 4) & 31;
    int idx  = i & 15;
    int nt = idx >> 1, j = idx & 1;
    int g = lane >> 2, t = lane & 3;
    int n = wn * 64 + nt * 8 + g;
    int k = half * 128 + ks * 16 + 2 * t + 8 * j;
    __half2 h = __floats2half2_rn(W[n * 256 + k], W[n * 256 + k + 1]);
    g_Bf16[i] = *(uint32_t*)&h;
}

__device__ __forceinline__ uint32_t smem_u32(const void* p) {
    uint32_t a;
    asm("{ .reg .u64 t; cvta.to.shared.u64 t, %1; cvt.u32.u64 %0, t; }" : "=r"(a) : "l"(p));
    return a;
}
__device__ __forceinline__ void cp16(uint32_t dst, const float* src) {
    asm volatile("cp.async.cg.shared.global [%0], [%1], 16;" :: "r"(dst), "l"(src));
}
__device__ __forceinline__ uint32_t pack_h2(float2 v) {
    __half2 h = __floats2half2_rn(v.x, v.y);
    return *(uint32_t*)&h;
}
__device__ __forceinline__ void mma16(float* acc, uint32_t a0, uint32_t a1,
                                      uint32_t a2, uint32_t a3,
                                      uint32_t b0, uint32_t b1) {
    asm volatile(
        "mma.sync.aligned.m16n8k16.row.col.f32.f16.f16.f32 "
        "{%0,%1,%2,%3}, {%4,%5,%6,%7}, {%8,%9}, {%0,%1,%2,%3};\n"
        : "+f"(acc[0]), "+f"(acc[1]), "+f"(acc[2]), "+f"(acc[3])
        : "r"(a0), "r"(a1), "r"(a2), "r"(a3), "r"(b0), "r"(b1));
}

// Shared GEMM body: 128x128 tile, K=128 (2 chunks of 64), 4 warps (2Mx2N),
// warp tile 64x64. HALF selects B table half (0 = Wh, 1 = We).
// MODE 0: out = A@B^T (G kernel, guarded rows)
// MODE 1: out = A@B^T + bias + G[heads]  (E kernel)
template <int MODE>
__device__ __forceinline__ void gemm_body(
    const float* __restrict__ Asrc_base,   // H or E
    const int*   __restrict__ heads,       // MODE 1 only
    const float* __restrict__ bias,        // MODE 1 only
    float*       __restrict__ outp,        // g_G or out
    int n_rows)                            // total A rows (guard)
{
    extern __shared__ __align__(16) float smem_f[];
    float* bias_s  = smem_f + 2 * ABUF;
    int*   heads_s = (int*)(bias_s + 128);
    const uint32_t s_abase = smem_u32(smem_f);

    const int tid  = threadIdx.x;
    const int warp = tid >> 5;
    const int lane = tid & 31;
    const int warp_m = warp >> 1;
    const int warp_n = warp & 1;
    const int g = lane >> 2;
    const int t = lane & 3;
    const int block_m = blockIdx.x * 128;

    if (MODE == 1 && tid < 128) {
        bias_s[tid]  = bias[tid];
        heads_s[tid] = heads[block_m + tid];
    }

    // A loads: thread -> one row, 64-float chunk (16 x cp16)
    int a_row_g = block_m + tid;
    if (MODE == 0 && a_row_g >= n_rows) a_row_g = n_rows - 1;  // clamp
    const float* srcA = Asrc_base + (size_t)a_row_g * 128;
    const uint32_t a_dst = s_abase + (uint32_t)(tid * SROW * 4);

    // prefetch both K-chunks
    #pragma unroll
    for (int cc = 0; cc < 2; cc++) {
        const float* src = srcA + cc * 64;
        uint32_t dst = a_dst + (uint32_t)(cc * ABUF * 4);
        #pragma unroll
        for (int i = 0; i < 16; i++) cp16(dst + i * 16, src + i * 4);
        asm volatile("cp.async.commit_group;" ::: "memory");
    }

    float acc[2][8][4];
    float acc2[2][8][4];
    #pragma unroll
    for (int mt = 0; mt < 2; mt++)
        #pragma unroll
        for (int nt = 0; nt < 8; nt++)
            #pragma unroll
            for (int i = 0; i < 4; i++) { acc[mt][nt][i] = 0.0f; acc2[mt][nt][i] = 0.0f; }

    const int HALF = (MODE == 0) ? 0 : 1;

    #pragma unroll 1
    for (int c = 0; c < 2; c++) {
        if (c == 0) asm volatile("cp.async.wait_group 1;" ::: "memory");
        else        asm volatile("cp.async.wait_group 0;" ::: "memory");
        __syncthreads();

        const float* Abuf = smem_f + c * ABUF;
        #pragma unroll
        for (int ksl = 0; ksl < 4; ksl++) {
            const int ks = c * 4 + ksl;          // 0..7
            const int kl2 = ksl * 16 + 2 * t;
            const uint4* bp = (const uint4*)g_Bf16 +
                (((HALF * 2 + warp_n) * 8 + ks) * 32 + lane) * 4;
            uint4 q0 = bp[0], q1 = bp[1], q2 = bp[2], q3 = bp[3];
            uint32_t bf[8][2] = {
                {q0.x, q0.y}, {q0.z, q0.w},
                {q1.x, q1.y}, {q1.z, q1.w},
                {q2.x, q2.y}, {q2.z, q2.w},
                {q3.x, q3.y}, {q3.z, q3.w}};
            #pragma unroll
            for (int mt = 0; mt < 4; mt++) {
                const int row0 = warp_m * 64 + mt * 16 + g;
                float2 p0 = *(const float2*)(Abuf + row0 * SROW + kl2);
                float2 p1 = *(const float2*)(Abuf + (row0 + 8) * SROW + kl2);
                float2 p2 = *(const float2*)(Abuf + row0 * SROW + kl2 + 8);
                float2 p3 = *(const float2*)(Abuf + (row0 + 8) * SROW + kl2 + 8);
                uint32_t a0 = pack_h2(p0);
                uint32_t a1 = pack_h2(p1);
                uint32_t a2 = pack_h2(p2);
                uint32_t a3 = pack_h2(p3);
                float* arow = (mt < 2) ? acc[mt][0] : acc2[mt - 2][0];
                #pragma unroll
                for (int nt = 0; nt < 8; nt++)
                    mma16(arow + nt * 4, a0, a1, a2, a3, bf[nt][0], bf[nt][1]);
            }
        }
        if (c == 0) __syncthreads();
    }

    // ---- Epilogue ----
    #pragma unroll
    for (int mt = 0; mt < 4; mt++) {
        const float* arow = (mt < 2) ? acc[mt][0] : acc2[mt - 2][0];
        const int r_lo = warp_m * 64 + mt * 16 + g;       // CTA-local rows
        const int r_hi = r_lo + 8;
        #pragma unroll
        for (int nt = 0; nt < 8; nt++) {
            const int col = warp_n * 64 + nt * 8 + t * 2;
            float2 v0, v1;
            v0.x = arow[nt * 4 + 0]; v0.y = arow[nt * 4 + 1];
            v1.x = arow[nt * 4 + 2]; v1.y = arow[nt * 4 + 3];
            if (MODE == 1) {
                float2 bv = *(const float2*)(bias_s + col);
                float2 g0 = *(const float2*)(g_G + (size_t)heads_s[r_lo] * 128 + col);
                float2 g1 = *(const float2*)(g_G + (size_t)heads_s[r_hi] * 128 + col);
                v0.x += bv.x + g0.x; v0.y += bv.y + g0.y;
                v1.x += bv.x + g1.x; v1.y += bv.y + g1.y;
                *(float2*)(outp + (size_t)(block_m + r_lo) * 128 + col) = v0;
                *(float2*)(outp + (size_t)(block_m + r_hi) * 128 + col) = v1;
            } else {
                if (block_m + r_lo < n_rows)
                    *(float2*)(outp + (size_t)(block_m + r_lo) * 128 + col) = v0;
                if (block_m + r_hi < n_rows)
                    *(float2*)(outp + (size_t)(block_m + r_hi) * 128 + col) = v1;
            }
        }
    }
}

__global__ void __launch_bounds__(128, 2) g_kernel(const float* __restrict__ H) {
    gemm_body<0>(H, nullptr, nullptr, g_G, N_NODES);
}

__global__ void __launch_bounds__(128, 2) e_kernel(
    const float* __restrict__ E,
    const int*   __restrict__ heads,
    const float* __restrict__ bias,
    float*       __restrict__ out)
{
    gemm_body<1>(E, heads, bias, out, 800000);
}

extern "C" void kernel_launch(void* const* d_in, const int* in_sizes, int n_in,
                              void* d_out, int out_size) {
    const float* H     = (const float*)d_in[0];
    const float* E     = (const float*)d_in[1];
    const int*   heads = (const int*)d_in[2];
    // d_in[3] = queries (unused)
    const float* W     = (const float*)d_in[4];
    const float* b     = (const float*)d_in[5];
    float* out = (float*)d_out;

    cudaFuncSetAttribute(g_kernel,
                         cudaFuncAttributeMaxDynamicSharedMemorySize, SMEM_BYTES);
    cudaFuncSetAttribute(e_kernel,
                         cudaFuncAttributeMaxDynamicSharedMemorySize, SMEM_BYTES);

    prep_b16<<<64, 256>>>(W);
    g_kernel<<<NBLOCKS_G, 128, SMEM_BYTES>>>(H);
    e_kernel<<<NBLOCKS_E, 128, SMEM_BYTES>>>(E, heads, b, out);
}

// round 8
// speedup vs baseline: 1.4178x; 1.4178x over previous
#include <cuda_runtime.h>
#include <cuda_fp16.h>
#include <cstdint>

#define NBLOCKS 6250
#define ACHUNK_BYTES (128 * 128)            // 128 rows x 64 fp16 cols
#define SMEM_BYTES (2 * ACHUNK_BYTES + 512)

// fp16 B fragments for mma.m16n8k16 (R4-proven layout):
// g_Bf16[(((wn*16 + ks)*32 + lane)*16) + nt*2 + j]
//   = half2(W[wn*64+nt*8+g][ks*16+2t+8j], W[...][...+1])
__device__ uint32_t g_Bf16[16384];          // 64 KB, L1/L2-resident

__global__ void prep_b16(const float* __restrict__ W) {
    int i = blockIdx.x * 256 + threadIdx.x;   // 0..16383
    int wn   = i >> 13;
    int rem  = i & 8191;
    int ks   = rem >> 9;
    int rem2 = rem & 511;
    int lane = rem2 >> 4;
    int idx  = rem2 & 15;
    int nt = idx >> 1, j = idx & 1;
    int g = lane >> 2, t = lane & 3;
    int n = wn * 64 + nt * 8 + g;
    int k = ks * 16 + 2 * t + 8 * j;
    __half2 h = __floats2half2_rn(W[n * 256 + k], W[n * 256 + k + 1]);
    g_Bf16[i] = *(uint32_t*)&h;
}

__device__ __forceinline__ uint32_t smem_u32(const void* p) {
    uint32_t a;
    asm("{ .reg .u64 t; cvta.to.shared.u64 t, %1; cvt.u32.u64 %0, t; }" : "=r"(a) : "l"(p));
    return a;
}
__device__ __forceinline__ uint32_t swz(uint32_t b) {   // 128B rows, 8-row period
    return b ^ (((b >> 7) & 7) << 4);
}
__device__ __forceinline__ uint32_t pack_h2(float x, float y) {
    __half2 h = __floats2half2_rn(x, y);
    return *(uint32_t*)&h;
}
__device__ __forceinline__ void ldsm4(uint32_t& a0, uint32_t& a1, uint32_t& a2,
                                      uint32_t& a3, uint32_t addr) {
    asm volatile("ldmatrix.sync.aligned.m8n8.x4.shared.b16 {%0,%1,%2,%3}, [%4];"
                 : "=r"(a0), "=r"(a1), "=r"(a2), "=r"(a3) : "r"(addr));
}
__device__ __forceinline__ void mma16(float* acc, uint32_t a0, uint32_t a1,
                                      uint32_t a2, uint32_t a3,
                                      uint32_t b0, uint32_t b1) {
    asm volatile(
        "mma.sync.aligned.m16n8k16.row.col.f32.f16.f16.f32 "
        "{%0,%1,%2,%3}, {%4,%5,%6,%7}, {%8,%9}, {%0,%1,%2,%3};\n"
        : "+f"(acc[0]), "+f"(acc[1]), "+f"(acc[2]), "+f"(acc[3])
        : "r"(a0), "r"(a1), "r"(a2), "r"(a3), "r"(b0), "r"(b1));
}

// CTA: 128 edges x 128 outputs. 128 threads = 4 warps (2M x 2N), 64x64 warp tile.
// A converted to fp16 at load (LDG->F2FP->STS, reg double-buffered), fragments
// via ldmatrix.x4 from swizzled smem. B fp16 fragments via LDG (L1-hot).
__global__ void __launch_bounds__(128, 2) msg_mma_kernel(
    const float* __restrict__ H,
    const float* __restrict__ E,
    const int*   __restrict__ heads,
    const float* __restrict__ bias,
    float*       __restrict__ out)
{
    extern __shared__ __align__(1024) char smem[];
    float* bias_s = (float*)(smem + 2 * ACHUNK_BYTES);
    const uint32_t sbase = smem_u32(smem);

    const int tid  = threadIdx.x;
    const int warp = tid >> 5;
    const int lane = tid & 31;
    const int warp_m = warp >> 1;
    const int warp_n = warp & 1;
    const int g = lane >> 2;
    const int t = lane & 3;
    const int block_m = blockIdx.x * 128;

    bias_s[tid] = bias[tid];

    // ---- A staging: thread covers rows (tid>>2)+32i, float cols (tid&3)*16.. ----
    const int arow = tid >> 2;
    const int aseg = (tid & 3) * 16;
    const float* hsrc[4];
    const float* esrc[4];
    uint32_t sts_a[4], sts_b[4];
    #pragma unroll
    for (int i = 0; i < 4; i++) {
        const int r = arow + 32 * i;
        hsrc[i] = H + (size_t)heads[block_m + r] * 128 + aseg;
        esrc[i] = E + (size_t)(block_m + r) * 128 + aseg;
        const uint32_t byt = (uint32_t)(r * 128 + aseg * 2);
        sts_a[i] = swz(byt);
        sts_b[i] = swz(byt + 16);
    }

    uint4 stg0[4][2], stg1[4][2];
    auto ldg_chunk = [&](int c, uint4 stg[4][2]) {
        #pragma unroll
        for (int i = 0; i < 4; i++) {
            const float* s = ((c < 2) ? hsrc[i] : esrc[i]) + (c & 1) * 64;
            float4 v0 = *(const float4*)(s + 0);
            float4 v1 = *(const float4*)(s + 4);
            float4 v2 = *(const float4*)(s + 8);
            float4 v3 = *(const float4*)(s + 12);
            stg[i][0] = make_uint4(pack_h2(v0.x, v0.y), pack_h2(v0.z, v0.w),
                                   pack_h2(v1.x, v1.y), pack_h2(v1.z, v1.w));
            stg[i][1] = make_uint4(pack_h2(v2.x, v2.y), pack_h2(v2.z, v2.w),
                                   pack_h2(v3.x, v3.y), pack_h2(v3.z, v3.w));
        }
    };
    auto sts_chunk = [&](int buf, uint4 stg[4][2]) {
        const uint32_t off = (uint32_t)(buf * ACHUNK_BYTES);
        #pragma unroll
        for (int i = 0; i < 4; i++) {
            *(uint4*)(smem + off + sts_a[i]) = stg[i][0];
            *(uint4*)(smem + off + sts_b[i]) = stg[i][1];
        }
    };

    // ---- ldmatrix lane bases per mt: UNSWIZZLED; XOR mask applied at use.
    // (kb2 + ksl*32 <= 112 < 128 never carries into row bits, and row0 is a
    //  multiple of 16, so the swizzle mask is the constant (lane&7)<<4.)
    const int row_sel = (lane & 7) + ((lane >> 3) & 1) * 8;
    const int kb2     = ((lane >> 4) & 1) * 16;   // byte offset of k-half
    const uint32_t xmask = (uint32_t)((lane & 7) << 4);
    uint32_t lm[4];
    #pragma unroll
    for (int mt = 0; mt < 4; mt++) {
        const int row0 = warp_m * 64 + mt * 16;
        lm[mt] = sbase + (uint32_t)((row0 + row_sel) * 128 + kb2);
    }

    float acc[2][8][4];
    float acc2[2][8][4];
    #pragma unroll
    for (int mt = 0; mt < 2; mt++)
        #pragma unroll
        for (int nt = 0; nt < 8; nt++)
            #pragma unroll
            for (int i = 0; i < 4; i++) { acc[mt][nt][i] = 0.0f; acc2[mt][nt][i] = 0.0f; }

    auto compute = [&](int c) {
        const uint32_t bufoff = (uint32_t)((c & 1) * ACHUNK_BYTES);
        #pragma unroll
        for (int ksl = 0; ksl < 4; ksl++) {
            const int ks = c * 4 + ksl;
            const uint4* bp = (const uint4*)g_Bf16 + ((warp_n * 16 + ks) * 32 + lane) * 4;
            uint4 q0 = bp[0], q1 = bp[1], q2 = bp[2], q3 = bp[3];
            uint32_t bf[8][2] = {
                {q0.x, q0.y}, {q0.z, q0.w},
                {q1.x, q1.y}, {q1.z, q1.w},
                {q2.x, q2.y}, {q2.z, q2.w},
                {q3.x, q3.y}, {q3.z, q3.w}};
            #pragma unroll
            for (int mt = 0; mt < 4; mt++) {
                uint32_t a0, a1, a2, a3;
                ldsm4(a0, a1, a2, a3,
                      (lm[mt] + bufoff + (uint32_t)(ksl * 32)) ^ xmask);
                float* arow_p = (mt < 2) ? acc[mt][0] : acc2[mt - 2][0];
                #pragma unroll
                for (int nt = 0; nt < 8; nt++)
                    mma16(arow_p + nt * 4, a0, a1, a2, a3, bf[nt][0], bf[nt][1]);
            }
        }
    };

    // ---- pipeline: LDG of chunk c+2 hidden under compute of chunk c ----
    ldg_chunk(0, stg0); sts_chunk(0, stg0);
    ldg_chunk(1, stg1); sts_chunk(1, stg1);
    ldg_chunk(2, stg0);
    __syncthreads();
    compute(0);
    __syncthreads();
    sts_chunk(0, stg0);
    ldg_chunk(3, stg1);
    __syncthreads();
    compute(1);
    __syncthreads();
    sts_chunk(1, stg1);
    __syncthreads();
    compute(2);
    compute(3);

    // ---- Epilogue: +bias, fp32 stores ----
    #pragma unroll
    for (int mt = 0; mt < 4; mt++) {
        const float* arow_p = (mt < 2) ? acc[mt][0] : acc2[mt - 2][0];
        const int row0 = block_m + warp_m * 64 + mt * 16 + g;
        #pragma unroll
        for (int nt = 0; nt < 8; nt++) {
            const int col = warp_n * 64 + nt * 8 + t * 2;
            float2 bv = *(const float2*)(bias_s + col);
            float2 v0, v1;
            v0.x = arow_p[nt * 4 + 0] + bv.x;
            v0.y = arow_p[nt * 4 + 1] + bv.y;
            v1.x = arow_p[nt * 4 + 2] + bv.x;
            v1.y = arow_p[nt * 4 + 3] + bv.y;
            *(float2*)(out + (size_t)row0 * 128 + col)       = v0;
            *(float2*)(out + (size_t)(row0 + 8) * 128 + col) = v1;
        }
    }
}

extern "C" void kernel_launch(void* const* d_in, const int* in_sizes, int n_in,
                              void* d_out, int out_size) {
    const float* H     = (const float*)d_in[0];
    const float* E     = (const float*)d_in[1];
    const int*   heads = (const int*)d_in[2];
    // d_in[3] = queries (unused)
    const float* W     = (const float*)d_in[4];
    const float* b     = (const float*)d_in[5];
    float* out = (float*)d_out;

    cudaFuncSetAttribute(msg_mma_kernel,
                         cudaFuncAttributeMaxDynamicSharedMemorySize, SMEM_BYTES);

    prep_b16<<<64, 256>>>(W);
    msg_mma_kernel<<<NBLOCKS, 128, SMEM_BYTES>>>(H, E, heads, b, out);
}